// round 13
// baseline (speedup 1.0000x reference)
#include <cuda_runtime.h>
#include <cuda_bf16.h>
#include <cstdint>
#include <cstddef>

// ---------------------------------------------------------------------------
// Problem constants
// ---------------------------------------------------------------------------
#define BATCH   256
#define SEQ     512
#define NIN     256
#define HID     256
#define G3      768
#define LAYERS  2
#define ROWS    (BATCH*SEQ)
#define RANKSUM 96

// ---------------------------------------------------------------------------
// Static device scratch (no cudaMalloc allowed)
// ---------------------------------------------------------------------------
__device__ float g_wx_buf[(size_t)ROWS * G3];
__device__ float g_x1[(size_t)ROWS * HID];
__device__ float g_P [LAYERS * NIN * RANKSUM];
__device__ float g_Q [LAYERS * RANKSUM * G3];
__device__ float g_Pu[LAYERS * HID * RANKSUM];
__device__ float g_Qu[LAYERS * RANKSUM * G3];
__device__ float g_Ueff[LAYERS * HID * G3];

// stage-1 output as bf16 hi/lo: [row][hi 96 | lo 96]  (384 B/row)
__device__ __nv_bfloat16 g_t16[(size_t)ROWS * 192];
// Q as bf16 hi/lo: [layer][n 768][hi 96 | lo 96]
__device__ __nv_bfloat16 g_q16[(size_t)LAYERS * G3 * 192];
// P^T as bf16 hi/lo: [layer][n 96][hi 256 | lo 256]
__device__ __nv_bfloat16 g_p16[(size_t)LAYERS * 96 * 512];

// U as bf16 hi/lo in B-operand layout: per (layer, cta): [96 n][264 k-padded]
#define BPAD  264                         // 528 bytes per row (bank step 4)
#define BTILE (96 * BPAD)                 // elems per (l, c) per precision
__device__ __nv_bfloat16 g_Uhi[(size_t)LAYERS * 8 * BTILE];
__device__ __nv_bfloat16 g_Ulo[(size_t)LAYERS * 8 * BTILE];

// h exchange (L2-resident): A-tile images [buf 2][group 16][hi 12288B | lo 12288B]
__device__ __nv_bfloat16 g_hx[2 * 16 * 2 * 6144];

// ---------------------------------------------------------------------------
// PTX helpers (baseline-target-safe: ldmatrix + mma.sync only)
// ---------------------------------------------------------------------------
__device__ __forceinline__ uint32_t smem_u32(const void* p)
{
    uint32_t a;
    asm("{ .reg .u64 t; cvta.to.shared.u64 t, %1; cvt.u32.u64 %0, t; }"
        : "=r"(a) : "l"(p));
    return a;
}

#define LDSM4(R, addr) \
    asm volatile("ldmatrix.sync.aligned.m8n8.x4.shared.b16 {%0,%1,%2,%3}, [%4];" \
        : "=r"((R)[0]), "=r"((R)[1]), "=r"((R)[2]), "=r"((R)[3]) : "r"(addr))
#define MMA16816(D, A, B) \
    asm volatile("mma.sync.aligned.m16n8k16.row.col.f32.bf16.bf16.f32 " \
        "{%0,%1,%2,%3}, {%4,%5,%6,%7}, {%8,%9}, {%0,%1,%2,%3};" \
        : "+f"((D)[0]), "+f"((D)[1]), "+f"((D)[2]), "+f"((D)[3]) \
        : "r"((A)[0]), "r"((A)[1]), "r"((A)[2]), "r"((A)[3]), \
          "r"((B)[0]), "r"((B)[1]))

// ---------------------------------------------------------------------------
// Pack kernel: concatenate low-rank factors
// ---------------------------------------------------------------------------
__global__ void pack_kernel(const float* __restrict__ Wd, const float* __restrict__ Wdg,
                            const float* __restrict__ Wo, const float* __restrict__ Wog,
                            const float* __restrict__ Ud, const float* __restrict__ Udg,
                            const float* __restrict__ Uo, const float* __restrict__ Uog)
{
    int idx = blockIdx.x * 256 + threadIdx.x;
    const int QN = LAYERS * RANKSUM * G3;
    const int PN = LAYERS * NIN * RANKSUM;
    if (idx < QN) {
        int l = idx / (RANKSUM * G3);
        int rem = idx - l * (RANKSUM * G3);
        int r = rem / G3, n = rem - r * G3;
        g_Q[idx]  = (r < 64) ? Wdg[(l*64 + r) * G3 + n] : Wog[(l*32 + (r-64)) * G3 + n];
        g_Qu[idx] = (r < 64) ? Udg[(l*64 + r) * G3 + n] : Uog[(l*32 + (r-64)) * G3 + n];
    }
    if (idx < PN) {
        int l = idx / (NIN * RANKSUM);
        int rem = idx - l * (NIN * RANKSUM);
        int k = rem / RANKSUM, j = rem - k * RANKSUM;
        g_P[idx]  = (j < 64) ? Wd[(l*NIN + k) * 64 + j] : Wo[(l*NIN + k) * 32 + (j-64)];
        g_Pu[idx] = (j < 64) ? Ud[(l*NIN + k) * 64 + j] : Uo[(l*NIN + k) * 32 + (j-64)];
    }
}

// ---------------------------------------------------------------------------
// Split Ueff (rnn B layout), Q (wx2 B layout), P^T (s1 B layout) into hi/lo.
// ---------------------------------------------------------------------------
__global__ void split_uq()
{
    int idx = blockIdx.x * 256 + threadIdx.x;
    const int UN = LAYERS * 8 * 96 * 256;      // 393216
    const int QN = LAYERS * G3 * 96;           // 147456
    const int PN = LAYERS * 96 * 256;          // 49152
    if (idx < UN) {
        int k = idx & 255;
        int n = (idx >> 8) % 96;
        int c = (idx >> 8) / 96 % 8;
        int l = idx / (8 * 96 * 256);
        int gatecol = ((n >> 5) << 8) + (c << 5) + (n & 31);
        float v = g_Ueff[(size_t)l * HID * G3 + (size_t)k * G3 + gatecol];
        __nv_bfloat16 hi = __float2bfloat16(v);
        __nv_bfloat16 lo = __float2bfloat16(v - __bfloat162float(hi));
        size_t o = ((size_t)l * 8 + c) * BTILE + n * BPAD + k;
        g_Uhi[o] = hi;
        g_Ulo[o] = lo;
    }
    if (idx < QN) {
        int k = idx % 96;
        int n = (idx / 96) % G3;
        int l = idx / (96 * G3);
        float v = g_Q[((size_t)l * RANKSUM + k) * G3 + n];
        __nv_bfloat16 hi = __float2bfloat16(v);
        __nv_bfloat16 lo = __float2bfloat16(v - __bfloat162float(hi));
        size_t o = ((size_t)l * G3 + n) * 192 + k;
        g_q16[o]      = hi;
        g_q16[o + 96] = lo;
    }
    if (idx < PN) {
        int k = idx & 255;
        int n = (idx >> 8) % 96;
        int l = idx / (96 * 256);
        float v = g_P[(size_t)l * NIN * RANKSUM + (size_t)k * RANKSUM + n];
        __nv_bfloat16 hi = __float2bfloat16(v);
        __nv_bfloat16 lo = __float2bfloat16(v - __bfloat162float(hi));
        size_t o = ((size_t)l * 96 + n) * 512 + k;
        g_p16[o]       = hi;
        g_p16[o + 256] = lo;
    }
}

// ---------------------------------------------------------------------------
// Ueff GEMM, both layers in one launch (blockIdx.z = layer)
// ---------------------------------------------------------------------------
__global__ void __launch_bounds__(256)
gemm_ueff(const float* __restrict__ Pu, const float* __restrict__ Qu,
          float* __restrict__ Ueff)
{
    __shared__ float As[16][64];
    __shared__ float Bs[16][68];

    const int l = blockIdx.z;
    const float* A = Pu + (size_t)l * HID * RANKSUM;
    const float* B = Qu + (size_t)l * RANKSUM * G3;
    float* C = Ueff + (size_t)l * HID * G3;

    const int tid = threadIdx.x;
    const int tm = tid >> 4, tn = tid & 15;
    const size_t bm = (size_t)blockIdx.x * 64;
    const int bn = blockIdx.y * 64;

    const int ar = tid >> 2, ak = (tid & 3) << 2;
    const int brow = tid >> 4, bcol = (tid & 15) << 2;

    float acc[4][4];
#pragma unroll
    for (int i = 0; i < 4; ++i)
#pragma unroll
        for (int j = 0; j < 4; ++j) acc[i][j] = 0.f;

    for (int k0 = 0; k0 < RANKSUM; k0 += 16) {
        float4 av = *(const float4*)(A + (bm + ar) * RANKSUM + k0 + ak);
        As[ak + 0][ar] = av.x; As[ak + 1][ar] = av.y;
        As[ak + 2][ar] = av.z; As[ak + 3][ar] = av.w;

        float4 bv = *(const float4*)(B + (size_t)(k0 + brow) * G3 + bn + bcol);
        *(float4*)&Bs[brow][bcol] = bv;
        __syncthreads();

#pragma unroll
        for (int k = 0; k < 16; ++k) {
            float4 a = *(const float4*)&As[k][tm << 2];
            float4 b = *(const float4*)&Bs[k][tn << 2];
            acc[0][0] = fmaf(a.x, b.x, acc[0][0]); acc[0][1] = fmaf(a.x, b.y, acc[0][1]);
            acc[0][2] = fmaf(a.x, b.z, acc[0][2]); acc[0][3] = fmaf(a.x, b.w, acc[0][3]);
            acc[1][0] = fmaf(a.y, b.x, acc[1][0]); acc[1][1] = fmaf(a.y, b.y, acc[1][1]);
            acc[1][2] = fmaf(a.y, b.z, acc[1][2]); acc[1][3] = fmaf(a.y, b.w, acc[1][3]);
            acc[2][0] = fmaf(a.z, b.x, acc[2][0]); acc[2][1] = fmaf(a.z, b.y, acc[2][1]);
            acc[2][2] = fmaf(a.z, b.z, acc[2][2]); acc[2][3] = fmaf(a.z, b.w, acc[2][3]);
            acc[3][0] = fmaf(a.w, b.x, acc[3][0]); acc[3][1] = fmaf(a.w, b.y, acc[3][1]);
            acc[3][2] = fmaf(a.w, b.z, acc[3][2]); acc[3][3] = fmaf(a.w, b.w, acc[3][3]);
        }
        __syncthreads();
    }

#pragma unroll
    for (int i = 0; i < 4; ++i) {
        size_t row = bm + (tm << 2) + i;
#pragma unroll
        for (int j = 0; j < 4; ++j)
            C[row * G3 + bn + (tn << 2) + j] = acc[i][j];
    }
}

// ---------------------------------------------------------------------------
// Stage-1 HMMA GEMM: T16[M,96] = x[M,256] @ P16^T  (unchanged R11)
// ---------------------------------------------------------------------------
#define S1_A_BYTES (128 * 272)
#define S1_B_BYTES (96 * 272)
#define S1_SMEM    (S1_A_BYTES + S1_B_BYTES)

__global__ void __launch_bounds__(256)
gemm_s1_hmma(const float* __restrict__ x,
             const __nv_bfloat16* __restrict__ P16,
             __nv_bfloat16* __restrict__ T16)
{
    extern __shared__ char sm[];
    char* sA = sm;
    char* sB = sm + S1_A_BYTES;

    const int tid = threadIdx.x;
    const int w = tid >> 5, lane = tid & 31;
    const int wm = w >> 1, wn = w & 1;
    const size_t bm = (size_t)blockIdx.x * 128;

    const uint32_t sAu = smem_u32(sA);
    const uint32_t sBu = smem_u32(sB);

    const int rr = lane & 7;
    const uint32_t aoff = (uint32_t)((wm * 32 + ((lane >> 3) & 1) * 8 + rr) * 272
                                     + (lane >> 4) * 16);
    const int q = lane >> 3;
    const uint32_t boff = (uint32_t)(rr * 272 + ((q >> 1) * 128) + (q & 1) * 16);

    float acc[2][6][4];
#pragma unroll
    for (int mt = 0; mt < 2; ++mt)
#pragma unroll
        for (int nt = 0; nt < 6; ++nt)
#pragma unroll
            for (int i = 0; i < 4; ++i) acc[mt][nt][i] = 0.f;

    const int crow = tid >> 1, chalf = tid & 1;

    for (int kc = 0; kc < 4; ++kc) {
        {
            const float4* src = (const float4*)(x + (bm + crow) * NIN
                                                + kc * 64 + chalf * 32);
            char* dst = sA + crow * 272 + chalf * 64;
#pragma unroll
            for (int i = 0; i < 8; ++i) {
                float4 v = src[i];
                __nv_bfloat16 h0 = __float2bfloat16(v.x);
                __nv_bfloat16 h1 = __float2bfloat16(v.y);
                __nv_bfloat16 h2 = __float2bfloat16(v.z);
                __nv_bfloat16 h3 = __float2bfloat16(v.w);
                __nv_bfloat16 l0 = __float2bfloat16(v.x - __bfloat162float(h0));
                __nv_bfloat16 l1 = __float2bfloat16(v.y - __bfloat162float(h1));
                __nv_bfloat16 l2 = __float2bfloat16(v.z - __bfloat162float(h2));
                __nv_bfloat16 l3 = __float2bfloat16(v.w - __bfloat162float(h3));
                uint32_t hw0 = (uint32_t)__bfloat16_as_ushort(h0) |
                               ((uint32_t)__bfloat16_as_ushort(h1) << 16);
                uint32_t hw1 = (uint32_t)__bfloat16_as_ushort(h2) |
                               ((uint32_t)__bfloat16_as_ushort(h3) << 16);
                uint32_t lw0 = (uint32_t)__bfloat16_as_ushort(l0) |
                               ((uint32_t)__bfloat16_as_ushort(l1) << 16);
                uint32_t lw1 = (uint32_t)__bfloat16_as_ushort(l2) |
                               ((uint32_t)__bfloat16_as_ushort(l3) << 16);
                *(uint32_t*)(dst + i * 8)           = hw0;
                *(uint32_t*)(dst + i * 8 + 4)       = hw1;
                *(uint32_t*)(dst + 128 + i * 8)     = lw0;
                *(uint32_t*)(dst + 128 + i * 8 + 4) = lw1;
            }
        }
        {
#pragma unroll
            for (int it = 0; it < 6; ++it) {
                int u = tid + 256 * it;
                int n = u >> 4;
                int part = (u >> 3) & 1;
                int i = u & 7;
                const uint4* src = (const uint4*)(P16 + (size_t)n * 512
                                                  + part * 256 + kc * 64) + i;
                *(uint4*)(sB + n * 272 + part * 128 + i * 16) = *src;
            }
        }
        __syncthreads();

#pragma unroll
        for (int kt = 0; kt < 4; ++kt) {
            uint32_t ahi[2][4], alo[2][4];
#pragma unroll
            for (int mt = 0; mt < 2; ++mt) {
                const uint32_t ab = sAu + aoff + (uint32_t)(mt * 16 * 272 + kt * 32);
                LDSM4(ahi[mt], ab);
                LDSM4(alo[mt], ab + 128);
            }
#pragma unroll
            for (int nt = 0; nt < 6; ++nt) {
                uint32_t bf[4];
                LDSM4(bf, sBu + boff + (uint32_t)((wn * 48 + nt * 8) * 272 + kt * 32));
#pragma unroll
                for (int mt = 0; mt < 2; ++mt) {
                    MMA16816(acc[mt][nt], ahi[mt], bf);
                    MMA16816(acc[mt][nt], alo[mt], bf);
                    MMA16816(acc[mt][nt], ahi[mt], bf + 2);
                }
            }
        }
        __syncthreads();
    }

    const int er = lane >> 2;
    const int ec = (lane & 3) << 1;
#pragma unroll
    for (int nt = 0; nt < 6; ++nt) {
        const int col = wn * 48 + nt * 8 + ec;
#pragma unroll
        for (int mt = 0; mt < 2; ++mt) {
#pragma unroll
            for (int rh = 0; rh < 2; ++rh) {
                const size_t row = bm + wm * 32 + mt * 16 + er + rh * 8;
                const float v0 = acc[mt][nt][rh * 2];
                const float v1 = acc[mt][nt][rh * 2 + 1];
                __nv_bfloat16 h0 = __float2bfloat16(v0);
                __nv_bfloat16 h1 = __float2bfloat16(v1);
                __nv_bfloat16 l0 = __float2bfloat16(v0 - __bfloat162float(h0));
                __nv_bfloat16 l1 = __float2bfloat16(v1 - __bfloat162float(h1));
                *(uint32_t*)(T16 + row * 192 + col) =
                    (uint32_t)__bfloat16_as_ushort(h0) |
                    ((uint32_t)__bfloat16_as_ushort(h1) << 16);
                *(uint32_t*)(T16 + row * 192 + 96 + col) =
                    (uint32_t)__bfloat16_as_ushort(l0) |
                    ((uint32_t)__bfloat16_as_ushort(l1) << 16);
            }
        }
    }
}

// ---------------------------------------------------------------------------
// Stage-2 HMMA GEMM: wx[M,768] = T16[M,96] @ Q16^T + bias  (unchanged)
// ---------------------------------------------------------------------------
#define WX2_A_BYTES (128 * 416)
#define WX2_B_BYTES (64 * 416)
#define WX2_SMEM    (WX2_A_BYTES + WX2_B_BYTES)

__global__ void __launch_bounds__(256)
wx2_hmma(const __nv_bfloat16* __restrict__ T16,
         const __nv_bfloat16* __restrict__ Q16,
         const float* __restrict__ bias,
         float* __restrict__ C)
{
    extern __shared__ char sm[];
    char* sA = sm;
    char* sB = sm + WX2_A_BYTES;

    const int tid = threadIdx.x;
    const int w = tid >> 5, lane = tid & 31;
    const int wm = w >> 1, wn = w & 1;
    const size_t bm = (size_t)blockIdx.y * 128;
    const int bn = blockIdx.x * 64;

    {
        const uint4* src = (const uint4*)T16 + bm * 24;
#pragma unroll
        for (int i = 0; i < 12; ++i) {
            int u = tid + 256 * i;
            int row = u / 24, ir = u - row * 24;
            uint32_t off = (uint32_t)(row * 416 + ir * 16 + ((ir >= 12) ? 16 : 0));
            *(uint4*)(sA + off) = src[u];
        }
        const uint4* srcB = (const uint4*)Q16 + (size_t)bn * 24;
#pragma unroll
        for (int i = 0; i < 6; ++i) {
            int u = tid + 256 * i;
            int row = u / 24, ir = u - row * 24;
            uint32_t off = (uint32_t)(row * 416 + ir * 16 + ((ir >= 12) ? 16 : 0));
            *(uint4*)(sB + off) = srcB[u];
        }
    }
    __syncthreads();

    const uint32_t sAu = smem_u32(sA);
    const uint32_t sBu = smem_u32(sB);

    const int rr = lane & 7;
    const uint32_t aoff = (uint32_t)((wm * 32 + ((lane >> 3) & 1) * 8 + rr) * 416
                                     + (lane >> 4) * 16);
    const int q = lane >> 3;
    const uint32_t boff = (uint32_t)((wn * 32 + rr) * 416 + (q & 1) * 16
                                     + (q >> 1) * 208);

    float acc[2][4][4];
#pragma unroll
    for (int mt = 0; mt < 2; ++mt)
#pragma unroll
        for (int nt = 0; nt < 4; ++nt)
#pragma unroll
            for (int i = 0; i < 4; ++i) acc[mt][nt][i] = 0.f;

#pragma unroll
    for (int kt = 0; kt < 6; ++kt) {
        uint32_t ahi[2][4], alo[2][4];
#pragma unroll
        for (int mt = 0; mt < 2; ++mt) {
            const uint32_t ab = sAu + aoff + (uint32_t)(mt * 16 * 416 + kt * 32);
            LDSM4(ahi[mt], ab);
            LDSM4(alo[mt], ab + 208);
        }
#pragma unroll
        for (int nt = 0; nt < 4; ++nt) {
            uint32_t bf[4];
            LDSM4(bf, sBu + boff + (uint32_t)(nt * 8 * 416 + kt * 32));
#pragma unroll
            for (int mt = 0; mt < 2; ++mt) {
                MMA16816(acc[mt][nt], ahi[mt], bf);
                MMA16816(acc[mt][nt], alo[mt], bf);
                MMA16816(acc[mt][nt], ahi[mt], bf + 2);
            }
        }
    }

    const int er = lane >> 2;
    const int ec = (lane & 3) << 1;
#pragma unroll
    for (int nt = 0; nt < 4; ++nt) {
        const int col = bn + wn * 32 + nt * 8 + ec;
        const float b0 = bias[col], b1 = bias[col + 1];
#pragma unroll
        for (int mt = 0; mt < 2; ++mt) {
            const size_t r0 = bm + wm * 32 + mt * 16 + er;
            *(float2*)(C + r0 * G3 + col) =
                make_float2(acc[mt][nt][0] + b0, acc[mt][nt][1] + b1);
            *(float2*)(C + (r0 + 8) * G3 + col) =
                make_float2(acc[mt][nt][2] + b0, acc[mt][nt][3] + b1);
        }
    }
}

__device__ __forceinline__ float sigmoidf_(float x)
{
    return __fdividef(1.f, 1.f + __expf(-x));
}
__device__ __forceinline__ float tanhf_(float x)
{
    return __fdividef(2.f, 1.f + __expf(-2.f * x)) - 1.f;
}

// ---------------------------------------------------------------------------
// HMMA recurrent kernel v6: R11 L2 exchange restored + spread epilogue.
// ALL 16 warps dump D partials to smem; each of 512 threads then owns ONE
// (row, col) h value: 12 scalar partial reads, one gate set, 2x2B publish,
// 1 output float. Uniform warp work -> lower cluster-barrier skew.
// ---------------------------------------------------------------------------
#define A_BYTES  24576
#define B_BYTES  (BTILE * 2)
#define RED_BYTES (16 * 32 * 12 * 4)      // 24576
#define RNN_SMEM (A_BYTES + 2 * B_BYTES + RED_BYTES)   // 150528

__global__ void __cluster_dims__(8, 1, 1) __launch_bounds__(512, 1)
rnn_hmma(const __nv_bfloat16* __restrict__ Uhi8,
         const __nv_bfloat16* __restrict__ Ulo8,
         const float* __restrict__ wx,
         float* __restrict__ out_x,
         float* __restrict__ hT_out,
         __nv_bfloat16* __restrict__ hx)
{
    extern __shared__ char sm[];
    char* sA  = sm;
    char* sBh = sm + A_BYTES;
    char* sBl = sBh + B_BYTES;
    float* red = (float*)(sBl + B_BYTES);   // [w 16][lane 32][12]

    const int c  = blockIdx.x & 7;
    const int g  = blockIdx.x >> 3;
    const int tid = threadIdx.x;
    const int w = tid >> 5, lane = tid & 31;
    const int kq = w >> 2;
    const int cg = w & 3;

    {
        const uint4* s0 = (const uint4*)(Uhi8 + (size_t)c * BTILE);
        const uint4* s1 = (const uint4*)(Ulo8 + (size_t)c * BTILE);
        uint4* d0 = (uint4*)sBh;
        uint4* d1 = (uint4*)sBl;
        for (int i = tid; i < B_BYTES / 16; i += 512) { d0[i] = s0[i]; d1[i] = s1[i]; }
        uint4 z4 = make_uint4(0u, 0u, 0u, 0u);
        uint4* a4 = (uint4*)sA;
        for (int i = tid; i < A_BYTES / 16; i += 512) a4[i] = z4;
    }
    __syncthreads();

    const uint32_t sAu  = smem_u32(sA);
    const uint32_t sBhu = smem_u32(sBh);
    const uint32_t sBlu = smem_u32(sBl);
    const int q = lane >> 3, rr = lane & 7;
    const uint32_t aoff = (uint32_t)(((q & 1) * 8 + rr) * 48 + (q >> 1) * 16);
    const uint32_t bbase = ((q < 2) ? sBhu : sBlu)
                         + (uint32_t)(rr * 528 + (q & 1) * 16)
                         + (uint32_t)((cg << 3) * 528);
    const uint32_t bz = 0, br = 32 * 528, bc = 64 * 528;

    // hoist B fragments (time-invariant) into registers
    uint32_t bZ[4][4], bR[4][4], bC[4][4];
#pragma unroll
    for (int i = 0; i < 4; ++i) {
        const uint32_t ko = bbase + (uint32_t)(((kq << 2) + i) * 32);
        LDSM4(bZ[i], ko + bz);
        LDSM4(bR[i], ko + br);
        LDSM4(bC[i], ko + bc);
    }

    // ---- spread-epilogue ownership: one h value per thread ----
    const int erow = w;                       // 0..15 (row within group)
    const int ecol = lane;                    // 0..31 (col within CTA slice)
    const int hidg = (c << 5) + ecol;
    const size_t brow = (size_t)(g * 16 + erow);
    const int ekt = hidg >> 4, ekin = hidg & 15;
    const uint32_t epo = (uint32_t)(ekt * 768 + erow * 48 + ekin * 2);
    // partial-read indices into D-fragment layout
    const int lsrc = (erow & 7) * 4 + ((ecol & 7) >> 1);
    const int ereg = ((erow >> 3) << 1) + (ecol & 1);
    const int ecg  = ecol >> 3;

    float hp = 0.f;

    // wx for step 0
    float wz, wr, wc;
    {
        const float* p = wx + (brow * SEQ) * G3 + hidg;
        wz = p[0]; wr = p[256]; wc = p[512];
    }

    for (int t = 0; t < SEQ; ++t) {
        // ---- prefetch wx for t+1 (hidden under MMA) ----
        float nz, nr, nc;
        {
            const int tn = (t + 1 < SEQ) ? t + 1 : t;
            const float* p = wx + (brow * SEQ + tn) * G3 + hidg;
            nz = p[0]; nr = p[256]; nc = p[512];
        }

        // ---- MMA over this warp's 4 k-tiles ----
        float dz[4] = {0.f, 0.f, 0.f, 0.f};
        float dr[4] = {0.f, 0.f, 0.f, 0.f};
        float dc[4] = {0.f, 0.f, 0.f, 0.f};
#pragma unroll
        for (int i = 0; i < 4; ++i) {
            const int ktl = (kq << 2) + i;
            uint32_t ah[4], al[4];
            const uint32_t ab = sAu + (uint32_t)(ktl * 768) + aoff;
            LDSM4(ah, ab);
            LDSM4(al, ab + 12288);

            MMA16816(dz, ah, bZ[i]);
            MMA16816(dz, al, bZ[i]);
            MMA16816(dz, ah, bZ[i] + 2);

            MMA16816(dr, ah, bR[i]);
            MMA16816(dr, al, bR[i]);
            MMA16816(dr, ah, bR[i] + 2);

            MMA16816(dc, ah, bC[i]);
            MMA16816(dc, al, bC[i]);
            MMA16816(dc, ah, bC[i] + 2);
        }

        // ---- ALL warps dump partials ----
        {
            float* s = red + (w * 32 + lane) * 12;
            *(float4*)(s + 0) = make_float4(dz[0], dz[1], dz[2], dz[3]);
            *(float4*)(s + 4) = make_float4(dr[0], dr[1], dr[2], dr[3]);
            *(float4*)(s + 8) = make_float4(dc[0], dc[1], dc[2], dc[3]);
        }
        __syncthreads();

        // ---- per-thread reduction + gates (one h value) ----
        float az = 0.f, ar2 = 0.f, ac = 0.f;
#pragma unroll
        for (int k2 = 0; k2 < 4; ++k2) {
            const float* sp = red + (((k2 << 2) + ecg) * 32 + lsrc) * 12;
            az  += sp[ereg];
            ar2 += sp[4 + ereg];
            ac  += sp[8 + ereg];
        }
        const float z  = sigmoidf_(wz + az);
        const float rg = sigmoidf_(wr + ar2);
        const float cc = tanhf_(wc + rg * ac);
        const float hn = z * hp + (1.f - z) * cc;
        hp = hn;

        // ---- publish bf16 hi/lo (2 x 2B, coalesced across the warp) ----
        {
            __nv_bfloat16 hh = __float2bfloat16(hn);
            __nv_bfloat16 hl = __float2bfloat16(hn - __bfloat162float(hh));
            const int nb = (t + 1) & 1;
            char* ex = (char*)hx + (size_t)(nb * 16 + g) * A_BYTES;
            *(__nv_bfloat16*)(ex + epo)         = hh;
            *(__nv_bfloat16*)(ex + 12288 + epo) = hl;
        }

        // cluster barrier (arrive releases publish stores)
        asm volatile("barrier.cluster.arrive.aligned;" ::: "memory");

        // outputs off the critical path
        out_x[(brow * SEQ + t) * HID + hidg] = hn;
        if (t == SEQ - 1)
            hT_out[brow * 512 + hidg] = hn;
        wz = nz; wr = nr; wc = nc;

        asm volatile("barrier.cluster.wait.aligned;" ::: "memory");

        // ---- reload full A image (linear 24KB copy, 512 threads) ----
        {
            const int nb = (t + 1) & 1;
            const uint4* src = (const uint4*)((const char*)hx +
                                              (size_t)(nb * 16 + g) * A_BYTES);
            uint4* dst = (uint4*)sA;
#pragma unroll
            for (int i = 0; i < 3; ++i)
                dst[tid + 512 * i] = src[tid + 512 * i];
        }
        __syncthreads();
    }
}

// ---------------------------------------------------------------------------
// Launch
// ---------------------------------------------------------------------------
extern "C" void kernel_launch(void* const* d_in, const int* in_sizes, int n_in,
                              void* d_out, int out_size)
{
    const float* x   = (const float*)d_in[0];
    const float* Wd  = (const float*)d_in[1];
    const float* Wdg = (const float*)d_in[2];
    const float* Wo  = (const float*)d_in[3];
    const float* Wog = (const float*)d_in[4];
    const float* Ud  = (const float*)d_in[5];
    const float* Udg = (const float*)d_in[6];
    const float* Uo  = (const float*)d_in[7];
    const float* Uog = (const float*)d_in[8];
    const float* bb  = (const float*)d_in[9];
    float* out = (float*)d_out;

    float *pWX, *pX1, *pP, *pQ, *pPu, *pQu, *pUeff;
    __nv_bfloat16 *pUhi, *pUlo, *pHX, *pT16, *pQ16, *pP16;
    cudaGetSymbolAddress((void**)&pWX,   g_wx_buf);
    cudaGetSymbolAddress((void**)&pX1,   g_x1);
    cudaGetSymbolAddress((void**)&pP,    g_P);
    cudaGetSymbolAddress((void**)&pQ,    g_Q);
    cudaGetSymbolAddress((void**)&pPu,   g_Pu);
    cudaGetSymbolAddress((void**)&pQu,   g_Qu);
    cudaGetSymbolAddress((void**)&pUeff, g_Ueff);
    cudaGetSymbolAddress((void**)&pUhi,  g_Uhi);
    cudaGetSymbolAddress((void**)&pUlo,  g_Ulo);
    cudaGetSymbolAddress((void**)&pHX,   g_hx);
    cudaGetSymbolAddress((void**)&pT16,  g_t16);
    cudaGetSymbolAddress((void**)&pQ16,  g_q16);
    cudaGetSymbolAddress((void**)&pP16,  g_p16);

    cudaFuncSetAttribute(rnn_hmma, cudaFuncAttributeMaxDynamicSharedMemorySize,
                         RNN_SMEM);
    cudaFuncSetAttribute(wx2_hmma, cudaFuncAttributeMaxDynamicSharedMemorySize,
                         WX2_SMEM);
    cudaFuncSetAttribute(gemm_s1_hmma, cudaFuncAttributeMaxDynamicSharedMemorySize,
                         S1_SMEM);

    pack_kernel<<<(LAYERS * RANKSUM * G3 + 255) / 256, 256>>>(Wd, Wdg, Wo, Wog,
                                                              Ud, Udg, Uo, Uog);
    gemm_ueff<<<dim3(HID / 64, G3 / 64, LAYERS), 256>>>(pPu, pQu, pUeff);
    split_uq<<<(LAYERS * 8 * 96 * 256 + 255) / 256, 256>>>();

    const size_t OUT0 = (size_t)ROWS * HID;

    for (int l = 0; l < LAYERS; ++l) {
        const float* xin = (l == 0) ? x : pX1;
        gemm_s1_hmma<<<ROWS / 128, 256, S1_SMEM>>>(
            xin, pP16 + (size_t)l * 96 * 512, pT16);
        wx2_hmma<<<dim3(G3 / 64, ROWS / 128), 256, WX2_SMEM>>>(
            pT16, pQ16 + (size_t)l * G3 * 192, bb + l * G3, pWX);
        float* ox = (l == LAYERS - 1) ? out : pX1;
        rnn_hmma<<<128, 512, RNN_SMEM>>>(
            pUhi + (size_t)l * 8 * BTILE, pUlo + (size_t)l * 8 * BTILE,
            pWX, ox, out + OUT0 + l * HID, pHX);
    }
}

// round 14
// speedup vs baseline: 1.1501x; 1.1501x over previous
#include <cuda_runtime.h>
#include <cuda_bf16.h>
#include <cstdint>
#include <cstddef>

// ---------------------------------------------------------------------------
// Problem constants
// ---------------------------------------------------------------------------
#define BATCH   256
#define SEQ     512
#define NIN     256
#define HID     256
#define G3      768
#define LAYERS  2
#define ROWS    (BATCH*SEQ)
#define RANKSUM 96

// ---------------------------------------------------------------------------
// Static device scratch (no cudaMalloc allowed)
// ---------------------------------------------------------------------------
__device__ float g_wx_buf[(size_t)ROWS * G3];
__device__ float g_x1[(size_t)ROWS * HID];
__device__ float g_P [LAYERS * NIN * RANKSUM];
__device__ float g_Q [LAYERS * RANKSUM * G3];
__device__ float g_Pu[LAYERS * HID * RANKSUM];
__device__ float g_Qu[LAYERS * RANKSUM * G3];
__device__ float g_Ueff[LAYERS * HID * G3];

// stage-1 output as bf16 hi/lo: [row][hi 96 | lo 96]  (384 B/row)
__device__ __nv_bfloat16 g_t16[(size_t)ROWS * 192];
// Q as bf16 hi/lo: [layer][n 768][hi 96 | lo 96]
__device__ __nv_bfloat16 g_q16[(size_t)LAYERS * G3 * 192];
// P^T as bf16 hi/lo: [layer][n 96][hi 256 | lo 256]
__device__ __nv_bfloat16 g_p16[(size_t)LAYERS * 96 * 512];

// U as bf16 hi/lo in B-operand layout: per (layer, cta): [96 n][264 k-padded]
#define BPAD  264                         // 528 bytes per row (bank step 4)
#define BTILE (96 * BPAD)                 // elems per (l, c) per precision
__device__ __nv_bfloat16 g_Uhi[(size_t)LAYERS * 8 * BTILE];
__device__ __nv_bfloat16 g_Ulo[(size_t)LAYERS * 8 * BTILE];

// h exchange (L2-resident): A-tile images [buf 2][group 16][hi 12288B | lo 12288B]
__device__ __nv_bfloat16 g_hx[2 * 16 * 2 * 6144];

// ---------------------------------------------------------------------------
// PTX helpers (baseline-target-safe: ldmatrix + mma.sync only)
// ---------------------------------------------------------------------------
__device__ __forceinline__ uint32_t smem_u32(const void* p)
{
    uint32_t a;
    asm("{ .reg .u64 t; cvta.to.shared.u64 t, %1; cvt.u32.u64 %0, t; }"
        : "=r"(a) : "l"(p));
    return a;
}

#define LDSM4(R, addr) \
    asm volatile("ldmatrix.sync.aligned.m8n8.x4.shared.b16 {%0,%1,%2,%3}, [%4];" \
        : "=r"((R)[0]), "=r"((R)[1]), "=r"((R)[2]), "=r"((R)[3]) : "r"(addr))
#define MMA16816(D, A, B) \
    asm volatile("mma.sync.aligned.m16n8k16.row.col.f32.bf16.bf16.f32 " \
        "{%0,%1,%2,%3}, {%4,%5,%6,%7}, {%8,%9}, {%0,%1,%2,%3};" \
        : "+f"((D)[0]), "+f"((D)[1]), "+f"((D)[2]), "+f"((D)[3]) \
        : "r"((A)[0]), "r"((A)[1]), "r"((A)[2]), "r"((A)[3]), \
          "r"((B)[0]), "r"((B)[1]))

// ---------------------------------------------------------------------------
// Pack kernel: concatenate low-rank factors
// ---------------------------------------------------------------------------
__global__ void pack_kernel(const float* __restrict__ Wd, const float* __restrict__ Wdg,
                            const float* __restrict__ Wo, const float* __restrict__ Wog,
                            const float* __restrict__ Ud, const float* __restrict__ Udg,
                            const float* __restrict__ Uo, const float* __restrict__ Uog)
{
    int idx = blockIdx.x * 256 + threadIdx.x;
    const int QN = LAYERS * RANKSUM * G3;
    const int PN = LAYERS * NIN * RANKSUM;
    if (idx < QN) {
        int l = idx / (RANKSUM * G3);
        int rem = idx - l * (RANKSUM * G3);
        int r = rem / G3, n = rem - r * G3;
        g_Q[idx]  = (r < 64) ? Wdg[(l*64 + r) * G3 + n] : Wog[(l*32 + (r-64)) * G3 + n];
        g_Qu[idx] = (r < 64) ? Udg[(l*64 + r) * G3 + n] : Uog[(l*32 + (r-64)) * G3 + n];
    }
    if (idx < PN) {
        int l = idx / (NIN * RANKSUM);
        int rem = idx - l * (NIN * RANKSUM);
        int k = rem / RANKSUM, j = rem - k * RANKSUM;
        g_P[idx]  = (j < 64) ? Wd[(l*NIN + k) * 64 + j] : Wo[(l*NIN + k) * 32 + (j-64)];
        g_Pu[idx] = (j < 64) ? Ud[(l*NIN + k) * 64 + j] : Uo[(l*NIN + k) * 32 + (j-64)];
    }
}

// ---------------------------------------------------------------------------
// Split Ueff (rnn B layout), Q (wx2 B layout), P^T (s1 B layout) into hi/lo.
// ---------------------------------------------------------------------------
__global__ void split_uq()
{
    int idx = blockIdx.x * 256 + threadIdx.x;
    const int UN = LAYERS * 8 * 96 * 256;      // 393216
    const int QN = LAYERS * G3 * 96;           // 147456
    const int PN = LAYERS * 96 * 256;          // 49152
    if (idx < UN) {
        int k = idx & 255;
        int n = (idx >> 8) % 96;
        int c = (idx >> 8) / 96 % 8;
        int l = idx / (8 * 96 * 256);
        int gatecol = ((n >> 5) << 8) + (c << 5) + (n & 31);
        float v = g_Ueff[(size_t)l * HID * G3 + (size_t)k * G3 + gatecol];
        __nv_bfloat16 hi = __float2bfloat16(v);
        __nv_bfloat16 lo = __float2bfloat16(v - __bfloat162float(hi));
        size_t o = ((size_t)l * 8 + c) * BTILE + n * BPAD + k;
        g_Uhi[o] = hi;
        g_Ulo[o] = lo;
    }
    if (idx < QN) {
        int k = idx % 96;
        int n = (idx / 96) % G3;
        int l = idx / (96 * G3);
        float v = g_Q[((size_t)l * RANKSUM + k) * G3 + n];
        __nv_bfloat16 hi = __float2bfloat16(v);
        __nv_bfloat16 lo = __float2bfloat16(v - __bfloat162float(hi));
        size_t o = ((size_t)l * G3 + n) * 192 + k;
        g_q16[o]      = hi;
        g_q16[o + 96] = lo;
    }
    if (idx < PN) {
        int k = idx & 255;
        int n = (idx >> 8) % 96;
        int l = idx / (96 * 256);
        float v = g_P[(size_t)l * NIN * RANKSUM + (size_t)k * RANKSUM + n];
        __nv_bfloat16 hi = __float2bfloat16(v);
        __nv_bfloat16 lo = __float2bfloat16(v - __bfloat162float(hi));
        size_t o = ((size_t)l * 96 + n) * 512 + k;
        g_p16[o]       = hi;
        g_p16[o + 256] = lo;
    }
}

// ---------------------------------------------------------------------------
// Ueff GEMM, both layers in one launch (blockIdx.z = layer)
// ---------------------------------------------------------------------------
__global__ void __launch_bounds__(256)
gemm_ueff(const float* __restrict__ Pu, const float* __restrict__ Qu,
          float* __restrict__ Ueff)
{
    __shared__ float As[16][64];
    __shared__ float Bs[16][68];

    const int l = blockIdx.z;
    const float* A = Pu + (size_t)l * HID * RANKSUM;
    const float* B = Qu + (size_t)l * RANKSUM * G3;
    float* C = Ueff + (size_t)l * HID * G3;

    const int tid = threadIdx.x;
    const int tm = tid >> 4, tn = tid & 15;
    const size_t bm = (size_t)blockIdx.x * 64;
    const int bn = blockIdx.y * 64;

    const int ar = tid >> 2, ak = (tid & 3) << 2;
    const int brow = tid >> 4, bcol = (tid & 15) << 2;

    float acc[4][4];
#pragma unroll
    for (int i = 0; i < 4; ++i)
#pragma unroll
        for (int j = 0; j < 4; ++j) acc[i][j] = 0.f;

    for (int k0 = 0; k0 < RANKSUM; k0 += 16) {
        float4 av = *(const float4*)(A + (bm + ar) * RANKSUM + k0 + ak);
        As[ak + 0][ar] = av.x; As[ak + 1][ar] = av.y;
        As[ak + 2][ar] = av.z; As[ak + 3][ar] = av.w;

        float4 bv = *(const float4*)(B + (size_t)(k0 + brow) * G3 + bn + bcol);
        *(float4*)&Bs[brow][bcol] = bv;
        __syncthreads();

#pragma unroll
        for (int k = 0; k < 16; ++k) {
            float4 a = *(const float4*)&As[k][tm << 2];
            float4 b = *(const float4*)&Bs[k][tn << 2];
            acc[0][0] = fmaf(a.x, b.x, acc[0][0]); acc[0][1] = fmaf(a.x, b.y, acc[0][1]);
            acc[0][2] = fmaf(a.x, b.z, acc[0][2]); acc[0][3] = fmaf(a.x, b.w, acc[0][3]);
            acc[1][0] = fmaf(a.y, b.x, acc[1][0]); acc[1][1] = fmaf(a.y, b.y, acc[1][1]);
            acc[1][2] = fmaf(a.y, b.z, acc[1][2]); acc[1][3] = fmaf(a.y, b.w, acc[1][3]);
            acc[2][0] = fmaf(a.z, b.x, acc[2][0]); acc[2][1] = fmaf(a.z, b.y, acc[2][1]);
            acc[2][2] = fmaf(a.z, b.z, acc[2][2]); acc[2][3] = fmaf(a.z, b.w, acc[2][3]);
            acc[3][0] = fmaf(a.w, b.x, acc[3][0]); acc[3][1] = fmaf(a.w, b.y, acc[3][1]);
            acc[3][2] = fmaf(a.w, b.z, acc[3][2]); acc[3][3] = fmaf(a.w, b.w, acc[3][3]);
        }
        __syncthreads();
    }

#pragma unroll
    for (int i = 0; i < 4; ++i) {
        size_t row = bm + (tm << 2) + i;
#pragma unroll
        for (int j = 0; j < 4; ++j)
            C[row * G3 + bn + (tn << 2) + j] = acc[i][j];
    }
}

// ---------------------------------------------------------------------------
// Stage-1 HMMA GEMM: T16[M,96] = x[M,256] @ P16^T
// R14: __launch_bounds__(256, 2) — regs capped at 128 (was 112), 2 CTAs/SM,
// doubles warps/SMSP to hide the LDSM->MMA chains (occ was 23%, issue 15%).
// ---------------------------------------------------------------------------
#define S1_A_BYTES (128 * 272)
#define S1_B_BYTES (96 * 272)
#define S1_SMEM    (S1_A_BYTES + S1_B_BYTES)

__global__ void __launch_bounds__(256, 2)
gemm_s1_hmma(const float* __restrict__ x,
             const __nv_bfloat16* __restrict__ P16,
             __nv_bfloat16* __restrict__ T16)
{
    extern __shared__ char sm[];
    char* sA = sm;
    char* sB = sm + S1_A_BYTES;

    const int tid = threadIdx.x;
    const int w = tid >> 5, lane = tid & 31;
    const int wm = w >> 1, wn = w & 1;
    const size_t bm = (size_t)blockIdx.x * 128;

    const uint32_t sAu = smem_u32(sA);
    const uint32_t sBu = smem_u32(sB);

    const int rr = lane & 7;
    const uint32_t aoff = (uint32_t)((wm * 32 + ((lane >> 3) & 1) * 8 + rr) * 272
                                     + (lane >> 4) * 16);
    const int q = lane >> 3;
    const uint32_t boff = (uint32_t)(rr * 272 + ((q >> 1) * 128) + (q & 1) * 16);

    float acc[2][6][4];
#pragma unroll
    for (int mt = 0; mt < 2; ++mt)
#pragma unroll
        for (int nt = 0; nt < 6; ++nt)
#pragma unroll
            for (int i = 0; i < 4; ++i) acc[mt][nt][i] = 0.f;

    const int crow = tid >> 1, chalf = tid & 1;

    for (int kc = 0; kc < 4; ++kc) {
        {
            const float4* src = (const float4*)(x + (bm + crow) * NIN
                                                + kc * 64 + chalf * 32);
            char* dst = sA + crow * 272 + chalf * 64;
#pragma unroll
            for (int i = 0; i < 8; ++i) {
                float4 v = src[i];
                __nv_bfloat16 h0 = __float2bfloat16(v.x);
                __nv_bfloat16 h1 = __float2bfloat16(v.y);
                __nv_bfloat16 h2 = __float2bfloat16(v.z);
                __nv_bfloat16 h3 = __float2bfloat16(v.w);
                __nv_bfloat16 l0 = __float2bfloat16(v.x - __bfloat162float(h0));
                __nv_bfloat16 l1 = __float2bfloat16(v.y - __bfloat162float(h1));
                __nv_bfloat16 l2 = __float2bfloat16(v.z - __bfloat162float(h2));
                __nv_bfloat16 l3 = __float2bfloat16(v.w - __bfloat162float(h3));
                uint32_t hw0 = (uint32_t)__bfloat16_as_ushort(h0) |
                               ((uint32_t)__bfloat16_as_ushort(h1) << 16);
                uint32_t hw1 = (uint32_t)__bfloat16_as_ushort(h2) |
                               ((uint32_t)__bfloat16_as_ushort(h3) << 16);
                uint32_t lw0 = (uint32_t)__bfloat16_as_ushort(l0) |
                               ((uint32_t)__bfloat16_as_ushort(l1) << 16);
                uint32_t lw1 = (uint32_t)__bfloat16_as_ushort(l2) |
                               ((uint32_t)__bfloat16_as_ushort(l3) << 16);
                *(uint32_t*)(dst + i * 8)           = hw0;
                *(uint32_t*)(dst + i * 8 + 4)       = hw1;
                *(uint32_t*)(dst + 128 + i * 8)     = lw0;
                *(uint32_t*)(dst + 128 + i * 8 + 4) = lw1;
            }
        }
        {
#pragma unroll
            for (int it = 0; it < 6; ++it) {
                int u = tid + 256 * it;
                int n = u >> 4;
                int part = (u >> 3) & 1;
                int i = u & 7;
                const uint4* src = (const uint4*)(P16 + (size_t)n * 512
                                                  + part * 256 + kc * 64) + i;
                *(uint4*)(sB + n * 272 + part * 128 + i * 16) = *src;
            }
        }
        __syncthreads();

#pragma unroll
        for (int kt = 0; kt < 4; ++kt) {
            uint32_t ahi[2][4], alo[2][4];
#pragma unroll
            for (int mt = 0; mt < 2; ++mt) {
                const uint32_t ab = sAu + aoff + (uint32_t)(mt * 16 * 272 + kt * 32);
                LDSM4(ahi[mt], ab);
                LDSM4(alo[mt], ab + 128);
            }
#pragma unroll
            for (int nt = 0; nt < 6; ++nt) {
                uint32_t bf[4];
                LDSM4(bf, sBu + boff + (uint32_t)((wn * 48 + nt * 8) * 272 + kt * 32));
#pragma unroll
                for (int mt = 0; mt < 2; ++mt) {
                    MMA16816(acc[mt][nt], ahi[mt], bf);
                    MMA16816(acc[mt][nt], alo[mt], bf);
                    MMA16816(acc[mt][nt], ahi[mt], bf + 2);
                }
            }
        }
        __syncthreads();
    }

    const int er = lane >> 2;
    const int ec = (lane & 3) << 1;
#pragma unroll
    for (int nt = 0; nt < 6; ++nt) {
        const int col = wn * 48 + nt * 8 + ec;
#pragma unroll
        for (int mt = 0; mt < 2; ++mt) {
#pragma unroll
            for (int rh = 0; rh < 2; ++rh) {
                const size_t row = bm + wm * 32 + mt * 16 + er + rh * 8;
                const float v0 = acc[mt][nt][rh * 2];
                const float v1 = acc[mt][nt][rh * 2 + 1];
                __nv_bfloat16 h0 = __float2bfloat16(v0);
                __nv_bfloat16 h1 = __float2bfloat16(v1);
                __nv_bfloat16 l0 = __float2bfloat16(v0 - __bfloat162float(h0));
                __nv_bfloat16 l1 = __float2bfloat16(v1 - __bfloat162float(h1));
                *(uint32_t*)(T16 + row * 192 + col) =
                    (uint32_t)__bfloat16_as_ushort(h0) |
                    ((uint32_t)__bfloat16_as_ushort(h1) << 16);
                *(uint32_t*)(T16 + row * 192 + 96 + col) =
                    (uint32_t)__bfloat16_as_ushort(l0) |
                    ((uint32_t)__bfloat16_as_ushort(l1) << 16);
            }
        }
    }
}

// ---------------------------------------------------------------------------
// Stage-2 HMMA GEMM: wx[M,768] = T16[M,96] @ Q16^T + bias  (unchanged)
// ---------------------------------------------------------------------------
#define WX2_A_BYTES (128 * 416)
#define WX2_B_BYTES (64 * 416)
#define WX2_SMEM    (WX2_A_BYTES + WX2_B_BYTES)

__global__ void __launch_bounds__(256)
wx2_hmma(const __nv_bfloat16* __restrict__ T16,
         const __nv_bfloat16* __restrict__ Q16,
         const float* __restrict__ bias,
         float* __restrict__ C)
{
    extern __shared__ char sm[];
    char* sA = sm;
    char* sB = sm + WX2_A_BYTES;

    const int tid = threadIdx.x;
    const int w = tid >> 5, lane = tid & 31;
    const int wm = w >> 1, wn = w & 1;
    const size_t bm = (size_t)blockIdx.y * 128;
    const int bn = blockIdx.x * 64;

    {
        const uint4* src = (const uint4*)T16 + bm * 24;
#pragma unroll
        for (int i = 0; i < 12; ++i) {
            int u = tid + 256 * i;
            int row = u / 24, ir = u - row * 24;
            uint32_t off = (uint32_t)(row * 416 + ir * 16 + ((ir >= 12) ? 16 : 0));
            *(uint4*)(sA + off) = src[u];
        }
        const uint4* srcB = (const uint4*)Q16 + (size_t)bn * 24;
#pragma unroll
        for (int i = 0; i < 6; ++i) {
            int u = tid + 256 * i;
            int row = u / 24, ir = u - row * 24;
            uint32_t off = (uint32_t)(row * 416 + ir * 16 + ((ir >= 12) ? 16 : 0));
            *(uint4*)(sB + off) = srcB[u];
        }
    }
    __syncthreads();

    const uint32_t sAu = smem_u32(sA);
    const uint32_t sBu = smem_u32(sB);

    const int rr = lane & 7;
    const uint32_t aoff = (uint32_t)((wm * 32 + ((lane >> 3) & 1) * 8 + rr) * 416
                                     + (lane >> 4) * 16);
    const int q = lane >> 3;
    const uint32_t boff = (uint32_t)((wn * 32 + rr) * 416 + (q & 1) * 16
                                     + (q >> 1) * 208);

    float acc[2][4][4];
#pragma unroll
    for (int mt = 0; mt < 2; ++mt)
#pragma unroll
        for (int nt = 0; nt < 4; ++nt)
#pragma unroll
            for (int i = 0; i < 4; ++i) acc[mt][nt][i] = 0.f;

#pragma unroll
    for (int kt = 0; kt < 6; ++kt) {
        uint32_t ahi[2][4], alo[2][4];
#pragma unroll
        for (int mt = 0; mt < 2; ++mt) {
            const uint32_t ab = sAu + aoff + (uint32_t)(mt * 16 * 416 + kt * 32);
            LDSM4(ahi[mt], ab);
            LDSM4(alo[mt], ab + 208);
        }
#pragma unroll
        for (int nt = 0; nt < 4; ++nt) {
            uint32_t bf[4];
            LDSM4(bf, sBu + boff + (uint32_t)(nt * 8 * 416 + kt * 32));
#pragma unroll
            for (int mt = 0; mt < 2; ++mt) {
                MMA16816(acc[mt][nt], ahi[mt], bf);
                MMA16816(acc[mt][nt], alo[mt], bf);
                MMA16816(acc[mt][nt], ahi[mt], bf + 2);
            }
        }
    }

    const int er = lane >> 2;
    const int ec = (lane & 3) << 1;
#pragma unroll
    for (int nt = 0; nt < 4; ++nt) {
        const int col = bn + wn * 32 + nt * 8 + ec;
        const float b0 = bias[col], b1 = bias[col + 1];
#pragma unroll
        for (int mt = 0; mt < 2; ++mt) {
            const size_t r0 = bm + wm * 32 + mt * 16 + er;
            *(float2*)(C + r0 * G3 + col) =
                make_float2(acc[mt][nt][0] + b0, acc[mt][nt][1] + b1);
            *(float2*)(C + (r0 + 8) * G3 + col) =
                make_float2(acc[mt][nt][2] + b0, acc[mt][nt][3] + b1);
        }
    }
}

__device__ __forceinline__ float sigmoidf_(float x)
{
    return __fdividef(1.f, 1.f + __expf(-x));
}
__device__ __forceinline__ float tanhf_(float x)
{
    return __fdividef(2.f, 1.f + __expf(-2.f * x)) - 1.f;
}

// ---------------------------------------------------------------------------
// HMMA recurrent kernel — exact R11 winner (B fragments hoisted, L2 exchange).
// ---------------------------------------------------------------------------
#define A_BYTES  24576
#define B_BYTES  (BTILE * 2)
#define RED_BYTES (3 * 4 * 32 * 12 * 4)
#define RNN_SMEM (A_BYTES + 2 * B_BYTES + RED_BYTES)

__global__ void __cluster_dims__(8, 1, 1) __launch_bounds__(512, 1)
rnn_hmma(const __nv_bfloat16* __restrict__ Uhi8,
         const __nv_bfloat16* __restrict__ Ulo8,
         const float* __restrict__ wx,
         float* __restrict__ out_x,
         float* __restrict__ hT_out,
         __nv_bfloat16* __restrict__ hx)
{
    extern __shared__ char sm[];
    char* sA  = sm;
    char* sBh = sm + A_BYTES;
    char* sBl = sBh + B_BYTES;
    float* red = (float*)(sBl + B_BYTES);

    const int c  = blockIdx.x & 7;
    const int g  = blockIdx.x >> 3;
    const int tid = threadIdx.x;
    const int w = tid >> 5, lane = tid & 31;
    const int kq = w >> 2;
    const int cg = w & 3;

    {
        const uint4* s0 = (const uint4*)(Uhi8 + (size_t)c * BTILE);
        const uint4* s1 = (const uint4*)(Ulo8 + (size_t)c * BTILE);
        uint4* d0 = (uint4*)sBh;
        uint4* d1 = (uint4*)sBl;
        for (int i = tid; i < B_BYTES / 16; i += 512) { d0[i] = s0[i]; d1[i] = s1[i]; }
        uint4 z4 = make_uint4(0u, 0u, 0u, 0u);
        uint4* a4 = (uint4*)sA;
        for (int i = tid; i < A_BYTES / 16; i += 512) a4[i] = z4;
    }
    __syncthreads();

    const uint32_t sAu  = smem_u32(sA);
    const uint32_t sBhu = smem_u32(sBh);
    const uint32_t sBlu = smem_u32(sBl);
    const int q = lane >> 3, rr = lane & 7;
    const uint32_t aoff = (uint32_t)(((q & 1) * 8 + rr) * 48 + (q >> 1) * 16);
    const uint32_t bbase = ((q < 2) ? sBhu : sBlu)
                         + (uint32_t)(rr * 528 + (q & 1) * 16)
                         + (uint32_t)((cg << 3) * 528);
    const uint32_t bz = 0, br = 32 * 528, bc = 64 * 528;

    // hoist B fragments (time-invariant) into registers
    uint32_t bZ[4][4], bR[4][4], bC[4][4];
#pragma unroll
    for (int i = 0; i < 4; ++i) {
        const uint32_t ko = bbase + (uint32_t)(((kq << 2) + i) * 32);
        LDSM4(bZ[i], ko + bz);
        LDSM4(bR[i], ko + br);
        LDSM4(bC[i], ko + bc);
    }

    const int r1 = lane >> 2;
    const int coll = (cg << 3) + ((lane & 3) << 1);
    const int hidg = (c << 5) + coll;
    const size_t brow1 = (size_t)(g * 16 + r1);
    const size_t brow2 = brow1 + 8;
    const int kt = hidg >> 4, kin = hidg & 15;
    const uint32_t po1 = (uint32_t)(kt * 768 + r1 * 48 + kin * 2);
    const uint32_t po2 = po1 + 8 * 48;

    float hp[4] = {0.f, 0.f, 0.f, 0.f};

    float2 wxv[3][2];
    if (kq == 0) {
        const float* p1 = wx + (brow1 * SEQ) * G3 + hidg;
        const float* p2 = wx + (brow2 * SEQ) * G3 + hidg;
        wxv[0][0] = *(const float2*)(p1);       wxv[0][1] = *(const float2*)(p2);
        wxv[1][0] = *(const float2*)(p1 + 256); wxv[1][1] = *(const float2*)(p2 + 256);
        wxv[2][0] = *(const float2*)(p1 + 512); wxv[2][1] = *(const float2*)(p2 + 512);
    }

    for (int t = 0; t < SEQ; ++t) {
        float2 wxn[3][2];
        if (kq == 0) {
            const int tn = (t + 1 < SEQ) ? t + 1 : t;
            const float* p1 = wx + (brow1 * SEQ + tn) * G3 + hidg;
            const float* p2 = wx + (brow2 * SEQ + tn) * G3 + hidg;
            wxn[0][0] = *(const float2*)(p1);       wxn[0][1] = *(const float2*)(p2);
            wxn[1][0] = *(const float2*)(p1 + 256); wxn[1][1] = *(const float2*)(p2 + 256);
            wxn[2][0] = *(const float2*)(p1 + 512); wxn[2][1] = *(const float2*)(p2 + 512);
        }

        float dz[4] = {0.f, 0.f, 0.f, 0.f};
        float dr[4] = {0.f, 0.f, 0.f, 0.f};
        float dc[4] = {0.f, 0.f, 0.f, 0.f};
#pragma unroll
        for (int i = 0; i < 4; ++i) {
            const int ktl = (kq << 2) + i;
            uint32_t ah[4], al[4];
            const uint32_t ab = sAu + (uint32_t)(ktl * 768) + aoff;
            LDSM4(ah, ab);
            LDSM4(al, ab + 12288);

            MMA16816(dz, ah, bZ[i]);
            MMA16816(dz, al, bZ[i]);
            MMA16816(dz, ah, bZ[i] + 2);

            MMA16816(dr, ah, bR[i]);
            MMA16816(dr, al, bR[i]);
            MMA16816(dr, ah, bR[i] + 2);

            MMA16816(dc, ah, bC[i]);
            MMA16816(dc, al, bC[i]);
            MMA16816(dc, ah, bC[i] + 2);
        }

        if (kq) {
            float* s = red + (((kq - 1) * 4 + cg) * 32 + lane) * 12;
            *(float4*)(s + 0) = make_float4(dz[0], dz[1], dz[2], dz[3]);
            *(float4*)(s + 4) = make_float4(dr[0], dr[1], dr[2], dr[3]);
            *(float4*)(s + 8) = make_float4(dc[0], dc[1], dc[2], dc[3]);
        }
        __syncthreads();

        float hn[4];
        if (kq == 0) {
#pragma unroll
            for (int s3 = 0; s3 < 3; ++s3) {
                const float* s = red + ((s3 * 4 + cg) * 32 + lane) * 12;
                const float4 vz = *(const float4*)(s + 0);
                const float4 vr = *(const float4*)(s + 4);
                const float4 vc = *(const float4*)(s + 8);
                dz[0] += vz.x; dz[1] += vz.y; dz[2] += vz.z; dz[3] += vz.w;
                dr[0] += vr.x; dr[1] += vr.y; dr[2] += vr.z; dr[3] += vr.w;
                dc[0] += vc.x; dc[1] += vc.y; dc[2] += vc.z; dc[3] += vc.w;
            }

#pragma unroll
            for (int i = 0; i < 4; ++i) {
                const int rs = i >> 1;
                const float wzv = (i & 1) ? wxv[0][rs].y : wxv[0][rs].x;
                const float wrv = (i & 1) ? wxv[1][rs].y : wxv[1][rs].x;
                const float wcv = (i & 1) ? wxv[2][rs].y : wxv[2][rs].x;
                const float z  = sigmoidf_(wzv + dz[i]);
                const float rg = sigmoidf_(wrv + dr[i]);
                const float cc = tanhf_(wcv + rg * dc[i]);
                hn[i] = z * hp[i] + (1.f - z) * cc;
                hp[i] = hn[i];
            }

            const int nb = (t + 1) & 1;
            char* ex = (char*)hx + (size_t)(nb * 16 + g) * A_BYTES;
            uint32_t hw[2], lw[2];
#pragma unroll
            for (int s2 = 0; s2 < 2; ++s2) {
                __nv_bfloat16 h0 = __float2bfloat16(hn[2*s2]);
                __nv_bfloat16 h1 = __float2bfloat16(hn[2*s2+1]);
                __nv_bfloat16 l0 = __float2bfloat16(hn[2*s2]   - __bfloat162float(h0));
                __nv_bfloat16 l1 = __float2bfloat16(hn[2*s2+1] - __bfloat162float(h1));
                hw[s2] = (uint32_t)__bfloat16_as_ushort(h0) |
                         ((uint32_t)__bfloat16_as_ushort(h1) << 16);
                lw[s2] = (uint32_t)__bfloat16_as_ushort(l0) |
                         ((uint32_t)__bfloat16_as_ushort(l1) << 16);
            }
            *(uint32_t*)(ex + po1)         = hw[0];
            *(uint32_t*)(ex + po2)         = hw[1];
            *(uint32_t*)(ex + 12288 + po1) = lw[0];
            *(uint32_t*)(ex + 12288 + po2) = lw[1];
        }

        asm volatile("barrier.cluster.arrive.aligned;" ::: "memory");

        if (kq == 0) {
            float* o1 = out_x + (brow1 * SEQ + t) * HID + hidg;
            float* o2 = out_x + (brow2 * SEQ + t) * HID + hidg;
            *(float2*)o1 = make_float2(hn[0], hn[1]);
            *(float2*)o2 = make_float2(hn[2], hn[3]);
            if (t == SEQ - 1) {
                *(float2*)(hT_out + brow1 * 512 + hidg) = make_float2(hn[0], hn[1]);
                *(float2*)(hT_out + brow2 * 512 + hidg) = make_float2(hn[2], hn[3]);
            }
#pragma unroll
            for (int a3 = 0; a3 < 3; ++a3) {
                wxv[a3][0] = wxn[a3][0];
                wxv[a3][1] = wxn[a3][1];
            }
        }

        asm volatile("barrier.cluster.wait.aligned;" ::: "memory");

        {
            const int nb = (t + 1) & 1;
            const uint4* src = (const uint4*)((const char*)hx +
                                              (size_t)(nb * 16 + g) * A_BYTES);
            uint4* dst = (uint4*)sA;
#pragma unroll
            for (int i = 0; i < 3; ++i)
                dst[tid + 512 * i] = src[tid + 512 * i];
        }
        __syncthreads();
    }
}

// ---------------------------------------------------------------------------
// Launch
// ---------------------------------------------------------------------------
extern "C" void kernel_launch(void* const* d_in, const int* in_sizes, int n_in,
                              void* d_out, int out_size)
{
    const float* x   = (const float*)d_in[0];
    const float* Wd  = (const float*)d_in[1];
    const float* Wdg = (const float*)d_in[2];
    const float* Wo  = (const float*)d_in[3];
    const float* Wog = (const float*)d_in[4];
    const float* Ud  = (const float*)d_in[5];
    const float* Udg = (const float*)d_in[6];
    const float* Uo  = (const float*)d_in[7];
    const float* Uog = (const float*)d_in[8];
    const float* bb  = (const float*)d_in[9];
    float* out = (float*)d_out;

    float *pWX, *pX1, *pP, *pQ, *pPu, *pQu, *pUeff;
    __nv_bfloat16 *pUhi, *pUlo, *pHX, *pT16, *pQ16, *pP16;
    cudaGetSymbolAddress((void**)&pWX,   g_wx_buf);
    cudaGetSymbolAddress((void**)&pX1,   g_x1);
    cudaGetSymbolAddress((void**)&pP,    g_P);
    cudaGetSymbolAddress((void**)&pQ,    g_Q);
    cudaGetSymbolAddress((void**)&pPu,   g_Pu);
    cudaGetSymbolAddress((void**)&pQu,   g_Qu);
    cudaGetSymbolAddress((void**)&pUeff, g_Ueff);
    cudaGetSymbolAddress((void**)&pUhi,  g_Uhi);
    cudaGetSymbolAddress((void**)&pUlo,  g_Ulo);
    cudaGetSymbolAddress((void**)&pHX,   g_hx);
    cudaGetSymbolAddress((void**)&pT16,  g_t16);
    cudaGetSymbolAddress((void**)&pQ16,  g_q16);
    cudaGetSymbolAddress((void**)&pP16,  g_p16);

    cudaFuncSetAttribute(rnn_hmma, cudaFuncAttributeMaxDynamicSharedMemorySize,
                         RNN_SMEM);
    cudaFuncSetAttribute(wx2_hmma, cudaFuncAttributeMaxDynamicSharedMemorySize,
                         WX2_SMEM);
    cudaFuncSetAttribute(gemm_s1_hmma, cudaFuncAttributeMaxDynamicSharedMemorySize,
                         S1_SMEM);

    pack_kernel<<<(LAYERS * RANKSUM * G3 + 255) / 256, 256>>>(Wd, Wdg, Wo, Wog,
                                                              Ud, Udg, Uo, Uog);
    gemm_ueff<<<dim3(HID / 64, G3 / 64, LAYERS), 256>>>(pPu, pQu, pUeff);
    split_uq<<<(LAYERS * 8 * 96 * 256 + 255) / 256, 256>>>();

    const size_t OUT0 = (size_t)ROWS * HID;

    for (int l = 0; l < LAYERS; ++l) {
        const float* xin = (l == 0) ? x : pX1;
        gemm_s1_hmma<<<ROWS / 128, 256, S1_SMEM>>>(
            xin, pP16 + (size_t)l * 96 * 512, pT16);
        wx2_hmma<<<dim3(G3 / 64, ROWS / 128), 256, WX2_SMEM>>>(
            pT16, pQ16 + (size_t)l * G3 * 192, bb + l * G3, pWX);
        float* ox = (l == LAYERS - 1) ? out : pX1;
        rnn_hmma<<<128, 512, RNN_SMEM>>>(
            pUhi + (size_t)l * 8 * BTILE, pUlo + (size_t)l * 8 * BTILE,
            pWX, ox, out + OUT0 + l * HID, pHX);
    }
}

// round 15
// speedup vs baseline: 1.1800x; 1.0261x over previous
#include <cuda_runtime.h>
#include <cuda_bf16.h>
#include <cstdint>
#include <cstddef>

// ---------------------------------------------------------------------------
// Problem constants
// ---------------------------------------------------------------------------
#define BATCH   256
#define SEQ     512
#define NIN     256
#define HID     256
#define G3      768
#define LAYERS  2
#define ROWS    (BATCH*SEQ)
#define RANKSUM 96

// ---------------------------------------------------------------------------
// Static device scratch (no cudaMalloc allowed)
// ---------------------------------------------------------------------------
__device__ float g_wx_buf[(size_t)ROWS * G3];
__device__ float g_x1[(size_t)ROWS * HID];
__device__ float g_Pu[LAYERS * HID * RANKSUM];
__device__ float g_Qu[LAYERS * RANKSUM * G3];

// Q as bf16 hi/lo: [layer][n 768][hi 96 | lo 96]
__device__ __nv_bfloat16 g_q16[(size_t)LAYERS * G3 * 192];
// P^T as bf16 hi/lo: [layer][n 96][hi 256 | lo 256]
__device__ __nv_bfloat16 g_p16[(size_t)LAYERS * 96 * 512];

// U as bf16 hi/lo in B-operand layout: per (layer, cta): [96 n][264 k-padded]
#define BPAD  264                         // 528 bytes per row (bank step 4)
#define BTILE (96 * BPAD)                 // elems per (l, c) per precision
__device__ __nv_bfloat16 g_Uhi[(size_t)LAYERS * 8 * BTILE];
__device__ __nv_bfloat16 g_Ulo[(size_t)LAYERS * 8 * BTILE];

// h exchange (L2-resident): A-tile images [buf 2][group 16][hi 12288B | lo 12288B]
__device__ __nv_bfloat16 g_hx[2 * 16 * 2 * 6144];

// ---------------------------------------------------------------------------
// PTX helpers (baseline-target-safe: ldmatrix + mma.sync only)
// ---------------------------------------------------------------------------
__device__ __forceinline__ uint32_t smem_u32(const void* p)
{
    uint32_t a;
    asm("{ .reg .u64 t; cvta.to.shared.u64 t, %1; cvt.u32.u64 %0, t; }"
        : "=r"(a) : "l"(p));
    return a;
}

#define LDSM4(R, addr) \
    asm volatile("ldmatrix.sync.aligned.m8n8.x4.shared.b16 {%0,%1,%2,%3}, [%4];" \
        : "=r"((R)[0]), "=r"((R)[1]), "=r"((R)[2]), "=r"((R)[3]) : "r"(addr))
#define MMA16816(D, A, B) \
    asm volatile("mma.sync.aligned.m16n8k16.row.col.f32.bf16.bf16.f32 " \
        "{%0,%1,%2,%3}, {%4,%5,%6,%7}, {%8,%9}, {%0,%1,%2,%3};" \
        : "+f"((D)[0]), "+f"((D)[1]), "+f"((D)[2]), "+f"((D)[3]) \
        : "r"((A)[0]), "r"((A)[1]), "r"((A)[2]), "r"((A)[3]), \
          "r"((B)[0]), "r"((B)[1]))

__device__ __forceinline__ uint32_t pack_hi2(float a, float b, uint32_t& lo)
{
    __nv_bfloat16 h0 = __float2bfloat16(a);
    __nv_bfloat16 h1 = __float2bfloat16(b);
    __nv_bfloat16 l0 = __float2bfloat16(a - __bfloat162float(h0));
    __nv_bfloat16 l1 = __float2bfloat16(b - __bfloat162float(h1));
    lo = (uint32_t)__bfloat16_as_ushort(l0) |
         ((uint32_t)__bfloat16_as_ushort(l1) << 16);
    return (uint32_t)__bfloat16_as_ushort(h0) |
           ((uint32_t)__bfloat16_as_ushort(h1) << 16);
}

// ---------------------------------------------------------------------------
// Pack kernel: Pu/Qu (fp32, for ueff) + q16/p16 hi/lo (direct from inputs)
// ---------------------------------------------------------------------------
__global__ void pack_kernel(const float* __restrict__ Wd, const float* __restrict__ Wdg,
                            const float* __restrict__ Wo, const float* __restrict__ Wog,
                            const float* __restrict__ Ud, const float* __restrict__ Udg,
                            const float* __restrict__ Uo, const float* __restrict__ Uog)
{
    int idx = blockIdx.x * 256 + threadIdx.x;
    const int QN = LAYERS * RANKSUM * G3;      // 147456 (Qu, q16)
    const int PN = LAYERS * NIN * RANKSUM;     // 49152  (Pu)
    const int P16N = LAYERS * 96 * 256;        // 49152  (p16)
    if (idx < QN) {
        // Qu (recurrent gate factors, fp32 for ueff GEMM)
        int l = idx / (RANKSUM * G3);
        int rem = idx - l * (RANKSUM * G3);
        int r = rem / G3, n = rem - r * G3;
        g_Qu[idx] = (r < 64) ? Udg[(l*64 + r) * G3 + n] : Uog[(l*32 + (r-64)) * G3 + n];
        // q16: [l][n][hi k96 | lo k96], value = Q[l][k][n]
        int k = idx % 96;
        int n2 = (idx / 96) % G3;
        int l2 = idx / (96 * G3);
        float v = (k < 64) ? Wdg[(l2*64 + k) * G3 + n2]
                           : Wog[(l2*32 + (k-64)) * G3 + n2];
        __nv_bfloat16 hi = __float2bfloat16(v);
        __nv_bfloat16 lo = __float2bfloat16(v - __bfloat162float(hi));
        size_t o = ((size_t)l2 * G3 + n2) * 192 + k;
        g_q16[o]      = hi;
        g_q16[o + 96] = lo;
    }
    if (idx < PN) {
        int l = idx / (NIN * RANKSUM);
        int rem = idx - l * (NIN * RANKSUM);
        int k = rem / RANKSUM, j = rem - k * RANKSUM;
        g_Pu[idx] = (j < 64) ? Ud[(l*NIN + k) * 64 + j] : Uo[(l*NIN + k) * 32 + (j-64)];
    }
    if (idx < P16N) {
        // p16: [l][n 96][hi k256 | lo k256], value = P[l][k][n]
        int k = idx & 255;
        int n = (idx >> 8) % 96;
        int l = idx / (96 * 256);
        float v = (n < 64) ? Wd[(l*NIN + k) * 64 + n]
                           : Wo[(l*NIN + k) * 32 + (n-64)];
        __nv_bfloat16 hi = __float2bfloat16(v);
        __nv_bfloat16 lo = __float2bfloat16(v - __bfloat162float(hi));
        size_t o = ((size_t)l * 96 + n) * 512 + k;
        g_p16[o]       = hi;
        g_p16[o + 256] = lo;
    }
}

// ---------------------------------------------------------------------------
// Ueff GEMM with fused hi/lo B-layout split epilogue.
// Ueff[l] = Pu[l] @ Qu[l] (256 x 768, K=96); epilogue writes g_Uhi/g_Ulo.
// ---------------------------------------------------------------------------
__global__ void __launch_bounds__(256)
gemm_ueff(const float* __restrict__ Pu, const float* __restrict__ Qu)
{
    __shared__ float As[16][64];
    __shared__ float Bs[16][68];

    const int l = blockIdx.z;
    const float* A = Pu + (size_t)l * HID * RANKSUM;
    const float* B = Qu + (size_t)l * RANKSUM * G3;

    const int tid = threadIdx.x;
    const int tm = tid >> 4, tn = tid & 15;
    const int bm = blockIdx.x * 64;
    const int bn = blockIdx.y * 64;

    const int ar = tid >> 2, ak = (tid & 3) << 2;
    const int brow = tid >> 4, bcol = (tid & 15) << 2;

    float acc[4][4];
#pragma unroll
    for (int i = 0; i < 4; ++i)
#pragma unroll
        for (int j = 0; j < 4; ++j) acc[i][j] = 0.f;

    for (int k0 = 0; k0 < RANKSUM; k0 += 16) {
        float4 av = *(const float4*)(A + (bm + ar) * RANKSUM + k0 + ak);
        As[ak + 0][ar] = av.x; As[ak + 1][ar] = av.y;
        As[ak + 2][ar] = av.z; As[ak + 3][ar] = av.w;

        float4 bv = *(const float4*)(B + (size_t)(k0 + brow) * G3 + bn + bcol);
        *(float4*)&Bs[brow][bcol] = bv;
        __syncthreads();

#pragma unroll
        for (int k = 0; k < 16; ++k) {
            float4 a = *(const float4*)&As[k][tm << 2];
            float4 b = *(const float4*)&Bs[k][tn << 2];
            acc[0][0] = fmaf(a.x, b.x, acc[0][0]); acc[0][1] = fmaf(a.x, b.y, acc[0][1]);
            acc[0][2] = fmaf(a.x, b.z, acc[0][2]); acc[0][3] = fmaf(a.x, b.w, acc[0][3]);
            acc[1][0] = fmaf(a.y, b.x, acc[1][0]); acc[1][1] = fmaf(a.y, b.y, acc[1][1]);
            acc[1][2] = fmaf(a.y, b.z, acc[1][2]); acc[1][3] = fmaf(a.y, b.w, acc[1][3]);
            acc[2][0] = fmaf(a.z, b.x, acc[2][0]); acc[2][1] = fmaf(a.z, b.y, acc[2][1]);
            acc[2][2] = fmaf(a.z, b.z, acc[2][2]); acc[2][3] = fmaf(a.z, b.w, acc[2][3]);
            acc[3][0] = fmaf(a.w, b.x, acc[3][0]); acc[3][1] = fmaf(a.w, b.y, acc[3][1]);
            acc[3][2] = fmaf(a.w, b.z, acc[3][2]); acc[3][3] = fmaf(a.w, b.w, acc[3][3]);
        }
        __syncthreads();
    }

    // epilogue: split into hi/lo and write rnn B-operand layout directly
#pragma unroll
    for (int i = 0; i < 4; ++i) {
        int k = bm + (tm << 2) + i;               // hidden index (0..255)
#pragma unroll
        for (int j = 0; j < 4; ++j) {
            int col = bn + (tn << 2) + j;          // gatecol (0..767)
            int c = (col >> 5) & 7;
            int n = ((col >> 8) << 5) + (col & 31);
            float v = acc[i][j];
            __nv_bfloat16 hi = __float2bfloat16(v);
            __nv_bfloat16 lo = __float2bfloat16(v - __bfloat162float(hi));
            size_t o = ((size_t)l * 8 + c) * BTILE + n * BPAD + k;
            g_Uhi[o] = hi;
            g_Ulo[o] = lo;
        }
    }
}

// ---------------------------------------------------------------------------
// Fused stage-1 + stage-2 GEMM:
//   phase 1: T[128,96] = x[128,256] @ P16^T   (acc in registers)
//   T stored to smem as bf16 hi/lo in the phase-2 A layout (416B rows)
//   phase 2: wx[128,768] = T @ Q16^T + bias   (12 n-chunks of 64)
// Eliminates the T16 global round-trip and all phase-2 A-tile DRAM traffic.
// ---------------------------------------------------------------------------
#define FX_T_BYTES (128 * 416)            // 53248 (phase-2 A / phase-1 x-stage)
#define FX_B_BYTES (64 * 416)             // 26624 (phase-2 B / phase-1 P-stage)
#define FX_SMEM    (FX_T_BYTES + FX_B_BYTES)

__global__ void __launch_bounds__(256)
s1wx_hmma(const float* __restrict__ x,
          const __nv_bfloat16* __restrict__ P16,   // layer base
          const __nv_bfloat16* __restrict__ Q16,   // layer base
          const float* __restrict__ bias,          // layer base
          float* __restrict__ C)
{
    extern __shared__ char sm[];
    char* sT = sm;                    // phase-1 x-stage (272) / phase-2 A (416)
    char* sB = sm + FX_T_BYTES;       // phase-1 P-stage (272) / phase-2 B (416)

    const int tid = threadIdx.x;
    const int w = tid >> 5, lane = tid & 31;
    const int wm = w >> 1, wn = w & 1;
    const size_t bm = (size_t)blockIdx.x * 128;

    const uint32_t sTu = smem_u32(sT);
    const uint32_t sBu = smem_u32(sB);

    const int rr = lane & 7;
    const int q = lane >> 3;
    const int er = lane >> 2;
    const int ec = (lane & 3) << 1;

    // ================= phase 1: T = x @ P16^T =================
    {
        const uint32_t a1off = (uint32_t)((wm * 32 + ((lane >> 3) & 1) * 8 + rr) * 272
                                          + (lane >> 4) * 16);
        const uint32_t b1off = (uint32_t)(rr * 272 + ((q >> 1) * 128) + (q & 1) * 16);

        float acc1[2][6][4];
#pragma unroll
        for (int mt = 0; mt < 2; ++mt)
#pragma unroll
            for (int nt = 0; nt < 6; ++nt)
#pragma unroll
                for (int i = 0; i < 4; ++i) acc1[mt][nt][i] = 0.f;

        const int crow = tid >> 1, chalf = tid & 1;

        for (int kc = 0; kc < 4; ++kc) {
            // stage x chunk -> bf16 hi/lo in sT (272B rows)
            {
                const float4* src = (const float4*)(x + (bm + crow) * NIN
                                                    + kc * 64 + chalf * 32);
                char* dst = sT + crow * 272 + chalf * 64;
#pragma unroll
                for (int i = 0; i < 8; ++i) {
                    float4 v = src[i];
                    uint32_t lw0, lw1;
                    uint32_t hw0 = pack_hi2(v.x, v.y, lw0);
                    uint32_t hw1 = pack_hi2(v.z, v.w, lw1);
                    *(uint32_t*)(dst + i * 8)           = hw0;
                    *(uint32_t*)(dst + i * 8 + 4)       = hw1;
                    *(uint32_t*)(dst + 128 + i * 8)     = lw0;
                    *(uint32_t*)(dst + 128 + i * 8 + 4) = lw1;
                }
            }
            // stage P16 chunk -> sB (272B rows)
            {
#pragma unroll
                for (int it = 0; it < 6; ++it) {
                    int u = tid + 256 * it;
                    int n = u >> 4;
                    int part = (u >> 3) & 1;
                    int i = u & 7;
                    const uint4* src = (const uint4*)(P16 + (size_t)n * 512
                                                      + part * 256 + kc * 64) + i;
                    *(uint4*)(sB + n * 272 + part * 128 + i * 16) = *src;
                }
            }
            __syncthreads();

#pragma unroll
            for (int kt = 0; kt < 4; ++kt) {
                uint32_t ahi[2][4], alo[2][4];
#pragma unroll
                for (int mt = 0; mt < 2; ++mt) {
                    const uint32_t ab = sTu + a1off
                                      + (uint32_t)(mt * 16 * 272 + kt * 32);
                    LDSM4(ahi[mt], ab);
                    LDSM4(alo[mt], ab + 128);
                }
#pragma unroll
                for (int nt = 0; nt < 6; ++nt) {
                    uint32_t bf[4];
                    LDSM4(bf, sBu + b1off
                              + (uint32_t)((wn * 48 + nt * 8) * 272 + kt * 32));
#pragma unroll
                    for (int mt = 0; mt < 2; ++mt) {
                        MMA16816(acc1[mt][nt], ahi[mt], bf);
                        MMA16816(acc1[mt][nt], alo[mt], bf);
                        MMA16816(acc1[mt][nt], ahi[mt], bf + 2);
                    }
                }
            }
            __syncthreads();
        }

        // store T to smem in phase-2 A layout (hi at col*2, lo at 208+col*2)
#pragma unroll
        for (int nt = 0; nt < 6; ++nt) {
            const int col = wn * 48 + nt * 8 + ec;
#pragma unroll
            for (int mt = 0; mt < 2; ++mt) {
#pragma unroll
                for (int rh = 0; rh < 2; ++rh) {
                    const int rowl = wm * 32 + mt * 16 + er + rh * 8;
                    uint32_t lw;
                    uint32_t hw = pack_hi2(acc1[mt][nt][rh * 2],
                                           acc1[mt][nt][rh * 2 + 1], lw);
                    *(uint32_t*)(sT + rowl * 416 + col * 2)       = hw;
                    *(uint32_t*)(sT + rowl * 416 + 208 + col * 2) = lw;
                }
            }
        }
        __syncthreads();
    }

    // ================= phase 2: wx = T @ Q16^T + bias =================
    {
        const uint32_t a2off = (uint32_t)((wm * 32 + ((lane >> 3) & 1) * 8 + rr) * 416
                                          + (lane >> 4) * 16);
        const uint32_t b2off = (uint32_t)((wn * 32 + rr) * 416 + (q & 1) * 16
                                          + (q >> 1) * 208);

        for (int bnc = 0; bnc < 12; ++bnc) {
            // load Q chunk (64 n rows x 24 uint4)
            {
                const uint4* srcB = (const uint4*)Q16 + (size_t)(bnc * 64) * 24;
#pragma unroll
                for (int i = 0; i < 6; ++i) {
                    int u = tid + 256 * i;
                    int row = u / 24, ir = u - row * 24;
                    uint32_t off = (uint32_t)(row * 416 + ir * 16
                                              + ((ir >= 12) ? 16 : 0));
                    *(uint4*)(sB + off) = srcB[u];
                }
            }
            __syncthreads();

            float acc2[2][4][4];
#pragma unroll
            for (int mt = 0; mt < 2; ++mt)
#pragma unroll
                for (int nt = 0; nt < 4; ++nt)
#pragma unroll
                    for (int i = 0; i < 4; ++i) acc2[mt][nt][i] = 0.f;

#pragma unroll
            for (int kt = 0; kt < 6; ++kt) {
                uint32_t ahi[2][4], alo[2][4];
#pragma unroll
                for (int mt = 0; mt < 2; ++mt) {
                    const uint32_t ab = sTu + a2off
                                      + (uint32_t)(mt * 16 * 416 + kt * 32);
                    LDSM4(ahi[mt], ab);
                    LDSM4(alo[mt], ab + 208);
                }
#pragma unroll
                for (int nt = 0; nt < 4; ++nt) {
                    uint32_t bf[4];
                    LDSM4(bf, sBu + b2off + (uint32_t)(nt * 8 * 416 + kt * 32));
#pragma unroll
                    for (int mt = 0; mt < 2; ++mt) {
                        MMA16816(acc2[mt][nt], ahi[mt], bf);
                        MMA16816(acc2[mt][nt], alo[mt], bf);
                        MMA16816(acc2[mt][nt], ahi[mt], bf + 2);
                    }
                }
            }

            // epilogue: + bias, fp32 store to wx
#pragma unroll
            for (int nt = 0; nt < 4; ++nt) {
                const int col = bnc * 64 + wn * 32 + nt * 8 + ec;
                const float b0 = bias[col], b1 = bias[col + 1];
#pragma unroll
                for (int mt = 0; mt < 2; ++mt) {
                    const size_t r0 = bm + wm * 32 + mt * 16 + er;
                    *(float2*)(C + r0 * G3 + col) =
                        make_float2(acc2[mt][nt][0] + b0, acc2[mt][nt][1] + b1);
                    *(float2*)(C + (r0 + 8) * G3 + col) =
                        make_float2(acc2[mt][nt][2] + b0, acc2[mt][nt][3] + b1);
                }
            }
            __syncthreads();
        }
    }
}

__device__ __forceinline__ float sigmoidf_(float x)
{
    return __fdividef(1.f, 1.f + __expf(-x));
}
__device__ __forceinline__ float tanhf_(float x)
{
    return __fdividef(2.f, 1.f + __expf(-2.f * x)) - 1.f;
}

// ---------------------------------------------------------------------------
// HMMA recurrent kernel — exact R11 winner (B fragments hoisted, L2 exchange).
// ---------------------------------------------------------------------------
#define A_BYTES  24576
#define B_BYTES  (BTILE * 2)
#define RED_BYTES (3 * 4 * 32 * 12 * 4)
#define RNN_SMEM (A_BYTES + 2 * B_BYTES + RED_BYTES)

__global__ void __cluster_dims__(8, 1, 1) __launch_bounds__(512, 1)
rnn_hmma(const __nv_bfloat16* __restrict__ Uhi8,
         const __nv_bfloat16* __restrict__ Ulo8,
         const float* __restrict__ wx,
         float* __restrict__ out_x,
         float* __restrict__ hT_out,
         __nv_bfloat16* __restrict__ hx)
{
    extern __shared__ char sm[];
    char* sA  = sm;
    char* sBh = sm + A_BYTES;
    char* sBl = sBh + B_BYTES;
    float* red = (float*)(sBl + B_BYTES);

    const int c  = blockIdx.x & 7;
    const int g  = blockIdx.x >> 3;
    const int tid = threadIdx.x;
    const int w = tid >> 5, lane = tid & 31;
    const int kq = w >> 2;
    const int cg = w & 3;

    {
        const uint4* s0 = (const uint4*)(Uhi8 + (size_t)c * BTILE);
        const uint4* s1 = (const uint4*)(Ulo8 + (size_t)c * BTILE);
        uint4* d0 = (uint4*)sBh;
        uint4* d1 = (uint4*)sBl;
        for (int i = tid; i < B_BYTES / 16; i += 512) { d0[i] = s0[i]; d1[i] = s1[i]; }
        uint4 z4 = make_uint4(0u, 0u, 0u, 0u);
        uint4* a4 = (uint4*)sA;
        for (int i = tid; i < A_BYTES / 16; i += 512) a4[i] = z4;
    }
    __syncthreads();

    const uint32_t sAu  = smem_u32(sA);
    const uint32_t sBhu = smem_u32(sBh);
    const uint32_t sBlu = smem_u32(sBl);
    const int q = lane >> 3, rr = lane & 7;
    const uint32_t aoff = (uint32_t)(((q & 1) * 8 + rr) * 48 + (q >> 1) * 16);
    const uint32_t bbase = ((q < 2) ? sBhu : sBlu)
                         + (uint32_t)(rr * 528 + (q & 1) * 16)
                         + (uint32_t)((cg << 3) * 528);
    const uint32_t bz = 0, br = 32 * 528, bc = 64 * 528;

    uint32_t bZ[4][4], bR[4][4], bC[4][4];
#pragma unroll
    for (int i = 0; i < 4; ++i) {
        const uint32_t ko = bbase + (uint32_t)(((kq << 2) + i) * 32);
        LDSM4(bZ[i], ko + bz);
        LDSM4(bR[i], ko + br);
        LDSM4(bC[i], ko + bc);
    }

    const int r1 = lane >> 2;
    const int coll = (cg << 3) + ((lane & 3) << 1);
    const int hidg = (c << 5) + coll;
    const size_t brow1 = (size_t)(g * 16 + r1);
    const size_t brow2 = brow1 + 8;
    const int kt = hidg >> 4, kin = hidg & 15;
    const uint32_t po1 = (uint32_t)(kt * 768 + r1 * 48 + kin * 2);
    const uint32_t po2 = po1 + 8 * 48;

    float hp[4] = {0.f, 0.f, 0.f, 0.f};

    float2 wxv[3][2];
    if (kq == 0) {
        const float* p1 = wx + (brow1 * SEQ) * G3 + hidg;
        const float* p2 = wx + (brow2 * SEQ) * G3 + hidg;
        wxv[0][0] = *(const float2*)(p1);       wxv[0][1] = *(const float2*)(p2);
        wxv[1][0] = *(const float2*)(p1 + 256); wxv[1][1] = *(const float2*)(p2 + 256);
        wxv[2][0] = *(const float2*)(p1 + 512); wxv[2][1] = *(const float2*)(p2 + 512);
    }

    for (int t = 0; t < SEQ; ++t) {
        float2 wxn[3][2];
        if (kq == 0) {
            const int tn = (t + 1 < SEQ) ? t + 1 : t;
            const float* p1 = wx + (brow1 * SEQ + tn) * G3 + hidg;
            const float* p2 = wx + (brow2 * SEQ + tn) * G3 + hidg;
            wxn[0][0] = *(const float2*)(p1);       wxn[0][1] = *(const float2*)(p2);
            wxn[1][0] = *(const float2*)(p1 + 256); wxn[1][1] = *(const float2*)(p2 + 256);
            wxn[2][0] = *(const float2*)(p1 + 512); wxn[2][1] = *(const float2*)(p2 + 512);
        }

        float dz[4] = {0.f, 0.f, 0.f, 0.f};
        float dr[4] = {0.f, 0.f, 0.f, 0.f};
        float dc[4] = {0.f, 0.f, 0.f, 0.f};
#pragma unroll
        for (int i = 0; i < 4; ++i) {
            const int ktl = (kq << 2) + i;
            uint32_t ah[4], al[4];
            const uint32_t ab = sAu + (uint32_t)(ktl * 768) + aoff;
            LDSM4(ah, ab);
            LDSM4(al, ab + 12288);

            MMA16816(dz, ah, bZ[i]);
            MMA16816(dz, al, bZ[i]);
            MMA16816(dz, ah, bZ[i] + 2);

            MMA16816(dr, ah, bR[i]);
            MMA16816(dr, al, bR[i]);
            MMA16816(dr, ah, bR[i] + 2);

            MMA16816(dc, ah, bC[i]);
            MMA16816(dc, al, bC[i]);
            MMA16816(dc, ah, bC[i] + 2);
        }

        if (kq) {
            float* s = red + (((kq - 1) * 4 + cg) * 32 + lane) * 12;
            *(float4*)(s + 0) = make_float4(dz[0], dz[1], dz[2], dz[3]);
            *(float4*)(s + 4) = make_float4(dr[0], dr[1], dr[2], dr[3]);
            *(float4*)(s + 8) = make_float4(dc[0], dc[1], dc[2], dc[3]);
        }
        __syncthreads();

        float hn[4];
        if (kq == 0) {
#pragma unroll
            for (int s3 = 0; s3 < 3; ++s3) {
                const float* s = red + ((s3 * 4 + cg) * 32 + lane) * 12;
                const float4 vz = *(const float4*)(s + 0);
                const float4 vr = *(const float4*)(s + 4);
                const float4 vc = *(const float4*)(s + 8);
                dz[0] += vz.x; dz[1] += vz.y; dz[2] += vz.z; dz[3] += vz.w;
                dr[0] += vr.x; dr[1] += vr.y; dr[2] += vr.z; dr[3] += vr.w;
                dc[0] += vc.x; dc[1] += vc.y; dc[2] += vc.z; dc[3] += vc.w;
            }

#pragma unroll
            for (int i = 0; i < 4; ++i) {
                const int rs = i >> 1;
                const float wzv = (i & 1) ? wxv[0][rs].y : wxv[0][rs].x;
                const float wrv = (i & 1) ? wxv[1][rs].y : wxv[1][rs].x;
                const float wcv = (i & 1) ? wxv[2][rs].y : wxv[2][rs].x;
                const float z  = sigmoidf_(wzv + dz[i]);
                const float rg = sigmoidf_(wrv + dr[i]);
                const float cc = tanhf_(wcv + rg * dc[i]);
                hn[i] = z * hp[i] + (1.f - z) * cc;
                hp[i] = hn[i];
            }

            const int nb = (t + 1) & 1;
            char* ex = (char*)hx + (size_t)(nb * 16 + g) * A_BYTES;
            uint32_t hw[2], lw[2];
#pragma unroll
            for (int s2 = 0; s2 < 2; ++s2)
                hw[s2] = pack_hi2(hn[2*s2], hn[2*s2+1], lw[s2]);
            *(uint32_t*)(ex + po1)         = hw[0];
            *(uint32_t*)(ex + po2)         = hw[1];
            *(uint32_t*)(ex + 12288 + po1) = lw[0];
            *(uint32_t*)(ex + 12288 + po2) = lw[1];
        }

        asm volatile("barrier.cluster.arrive.aligned;" ::: "memory");

        if (kq == 0) {
            float* o1 = out_x + (brow1 * SEQ + t) * HID + hidg;
            float* o2 = out_x + (brow2 * SEQ + t) * HID + hidg;
            *(float2*)o1 = make_float2(hn[0], hn[1]);
            *(float2*)o2 = make_float2(hn[2], hn[3]);
            if (t == SEQ - 1) {
                *(float2*)(hT_out + brow1 * 512 + hidg) = make_float2(hn[0], hn[1]);
                *(float2*)(hT_out + brow2 * 512 + hidg) = make_float2(hn[2], hn[3]);
            }
#pragma unroll
            for (int a3 = 0; a3 < 3; ++a3) {
                wxv[a3][0] = wxn[a3][0];
                wxv[a3][1] = wxn[a3][1];
            }
        }

        asm volatile("barrier.cluster.wait.aligned;" ::: "memory");

        {
            const int nb = (t + 1) & 1;
            const uint4* src = (const uint4*)((const char*)hx +
                                              (size_t)(nb * 16 + g) * A_BYTES);
            uint4* dst = (uint4*)sA;
#pragma unroll
            for (int i = 0; i < 3; ++i)
                dst[tid + 512 * i] = src[tid + 512 * i];
        }
        __syncthreads();
    }
}

// ---------------------------------------------------------------------------
// Launch  (our launches: pack, ueff, s1wx, rnn, s1wx, rnn — rnn profiled @#4)
// ---------------------------------------------------------------------------
extern "C" void kernel_launch(void* const* d_in, const int* in_sizes, int n_in,
                              void* d_out, int out_size)
{
    const float* x   = (const float*)d_in[0];
    const float* Wd  = (const float*)d_in[1];
    const float* Wdg = (const float*)d_in[2];
    const float* Wo  = (const float*)d_in[3];
    const float* Wog = (const float*)d_in[4];
    const float* Ud  = (const float*)d_in[5];
    const float* Udg = (const float*)d_in[6];
    const float* Uo  = (const float*)d_in[7];
    const float* Uog = (const float*)d_in[8];
    const float* bb  = (const float*)d_in[9];
    float* out = (float*)d_out;

    float *pWX, *pX1, *pPu, *pQu;
    __nv_bfloat16 *pUhi, *pUlo, *pHX, *pQ16, *pP16;
    cudaGetSymbolAddress((void**)&pWX,   g_wx_buf);
    cudaGetSymbolAddress((void**)&pX1,   g_x1);
    cudaGetSymbolAddress((void**)&pPu,   g_Pu);
    cudaGetSymbolAddress((void**)&pQu,   g_Qu);
    cudaGetSymbolAddress((void**)&pUhi,  g_Uhi);
    cudaGetSymbolAddress((void**)&pUlo,  g_Ulo);
    cudaGetSymbolAddress((void**)&pHX,   g_hx);
    cudaGetSymbolAddress((void**)&pQ16,  g_q16);
    cudaGetSymbolAddress((void**)&pP16,  g_p16);

    cudaFuncSetAttribute(rnn_hmma, cudaFuncAttributeMaxDynamicSharedMemorySize,
                         RNN_SMEM);
    cudaFuncSetAttribute(s1wx_hmma, cudaFuncAttributeMaxDynamicSharedMemorySize,
                         FX_SMEM);

    pack_kernel<<<(LAYERS * RANKSUM * G3 + 255) / 256, 256>>>(Wd, Wdg, Wo, Wog,
                                                              Ud, Udg, Uo, Uog);
    gemm_ueff<<<dim3(HID / 64, G3 / 64, LAYERS), 256>>>(pPu, pQu);

    const size_t OUT0 = (size_t)ROWS * HID;

    for (int l = 0; l < LAYERS; ++l) {
        const float* xin = (l == 0) ? x : pX1;
        s1wx_hmma<<<ROWS / 128, 256, FX_SMEM>>>(
            xin, pP16 + (size_t)l * 96 * 512, pQ16 + (size_t)l * G3 * 192,
            bb + l * G3, pWX);
        float* ox = (l == LAYERS - 1) ? out : pX1;
        rnn_hmma<<<128, 512, RNN_SMEM>>>(
            pUhi + (size_t)l * 8 * BTILE, pUlo + (size_t)l * 8 * BTILE,
            pWX, ox, out + OUT0 + l * HID, pHX);
    }
}